// round 12
// baseline (speedup 1.0000x reference)
#include <cuda_runtime.h>

// ---------------------------------------------------------------------------
// Problem constants (fixed by the reference): B=2, S=2048, D=2048, H=16, hd=128
// ---------------------------------------------------------------------------
constexpr int Bb = 2;
constexpr int S  = 2048;
constexpr int D  = 2048;
constexpr int H  = 16;
constexpr int HD = 128;
constexpr int MS = Bb * S;                       // 4096 rows for projections
constexpr size_t A_SIZE = (size_t)Bb * S * D;   // 8388608

typedef unsigned long long u64;

// ---------------------------------------------------------------------------
// Packed f32x2 helpers (sm_103a: FFMA-3reg is half-rate; fma.rn.f32x2 restores
// full fp32 throughput — PTX-only, ptxas never auto-fuses)
// ---------------------------------------------------------------------------
__device__ __forceinline__ u64 pack2(float x, float y) {
    u64 r; asm("mov.b64 %0, {%1,%2};" : "=l"(r) : "f"(x), "f"(y)); return r;
}
__device__ __forceinline__ void unpack2(u64 v, float &x, float &y) {
    asm("mov.b64 {%0,%1}, %2;" : "=f"(x), "=f"(y) : "l"(v));
}
__device__ __forceinline__ void fma2(u64 &c, u64 a, u64 b) {
    asm("fma.rn.f32x2 %0, %1, %2, %3;" : "=l"(c) : "l"(a), "l"(b), "l"(c));
}
__device__ __forceinline__ u64 mul2(u64 a, u64 b) {
    u64 r; asm("mul.rn.f32x2 %0, %1, %2;" : "=l"(r) : "l"(a), "l"(b)); return r;
}

// ---------------------------------------------------------------------------
// Scratch (static __device__ arrays — no allocation allowed in kernel_launch)
// ---------------------------------------------------------------------------
__device__ float g_q[A_SIZE];   // Q in [B,H,S,hd]
__device__ float g_a[A_SIZE];   // attention result, merged heads [B,S,D]
__device__ float g_k[A_SIZE];   // fallback if out buffer has no present region
__device__ float g_v[A_SIZE];

// ---------------------------------------------------------------------------
// SGEMM: C[M=4096, N=2048] = A[M,K=2048] @ W[K,N] + bias
// 128x128 tile, BK=16, 256 threads, 8x8 per thread via f32x2,
// double-buffered smem with register prefetch.
// mode 0: row-major write to Cout[m*D + n]
// mode 1: scatter to [B,H,S,hd]:  Cout[((b*H+h)*S+s)*hd + dd]
// ---------------------------------------------------------------------------
constexpr int BM = 128, BN = 128, BK = 16;

__global__ __launch_bounds__(256, 2)
void sgemm_kernel(const float* __restrict__ A, const float* __restrict__ Bw,
                  const float* __restrict__ bias, float* __restrict__ Cout,
                  int mode)
{
    __shared__ __align__(16) float As[2][BK][BM + 4];
    __shared__ __align__(16) float Bs[2][BK][BN + 4];

    const int tid  = threadIdx.x;
    const int tx   = tid & 15;        // 0..15 -> 8 cols each
    const int ty   = tid >> 4;        // 0..15 -> 8 rows each
    const int row0 = blockIdx.y * BM;
    const int n0   = blockIdx.x * BN;

    // A tile: 128 rows x 16 k = 512 float4; this thread does f and f+256
    const int ar0 = tid >> 2;                 // 0..63
    const int ak  = (tid & 3) * 4;            // 0,4,8,12
    const int ar1 = ar0 + 64;                 // (tid+256)>>2, ak unchanged
    // B tile: 16 k x 128 cols = 512 float4
    const int bk0 = tid >> 5;                 // 0..7
    const int bc0 = (tid & 31) * 4;           // 0..124
    const int bk1 = bk0 + 8;                  // (tid+256)>>5, bc unchanged

    // ---- stage tile 0 directly into smem buffer 0 ----
    {
        float4 a0 = *(const float4*)&A[(size_t)(row0 + ar0) * D + ak];
        float4 a1 = *(const float4*)&A[(size_t)(row0 + ar1) * D + ak];
        float4 b0 = *(const float4*)&Bw[(size_t)bk0 * D + n0 + bc0];
        float4 b1 = *(const float4*)&Bw[(size_t)bk1 * D + n0 + bc0];
        As[0][ak + 0][ar0] = a0.x; As[0][ak + 1][ar0] = a0.y;
        As[0][ak + 2][ar0] = a0.z; As[0][ak + 3][ar0] = a0.w;
        As[0][ak + 0][ar1] = a1.x; As[0][ak + 1][ar1] = a1.y;
        As[0][ak + 2][ar1] = a1.z; As[0][ak + 3][ar1] = a1.w;
        *(float4*)&Bs[0][bk0][bc0] = b0;
        *(float4*)&Bs[0][bk1][bc0] = b1;
    }
    __syncthreads();

    u64 c2[8][4];
    #pragma unroll
    for (int i = 0; i < 8; i++)
        #pragma unroll
        for (int j = 0; j < 4; j++) c2[i][j] = 0ull;

    constexpr int NT = D / BK;   // 128 k-tiles
    float4 pa0, pa1, pb0, pb1;

    for (int kt = 0; kt < NT; kt++) {
        const int cur = kt & 1;
        if (kt + 1 < NT) {
            const int k0 = (kt + 1) * BK;
            pa0 = *(const float4*)&A[(size_t)(row0 + ar0) * D + k0 + ak];
            pa1 = *(const float4*)&A[(size_t)(row0 + ar1) * D + k0 + ak];
            pb0 = *(const float4*)&Bw[(size_t)(k0 + bk0) * D + n0 + bc0];
            pb1 = *(const float4*)&Bw[(size_t)(k0 + bk1) * D + n0 + bc0];
        }
        #pragma unroll
        for (int k = 0; k < BK; k++) {
            const float4 a0 = *(const float4*)&As[cur][k][ty * 8];
            const float4 a1 = *(const float4*)&As[cur][k][ty * 8 + 4];
            const float4 b0 = *(const float4*)&Bs[cur][k][tx * 8];
            const float4 b1 = *(const float4*)&Bs[cur][k][tx * 8 + 4];
            u64 av[8];
            av[0] = pack2(a0.x, a0.x); av[1] = pack2(a0.y, a0.y);
            av[2] = pack2(a0.z, a0.z); av[3] = pack2(a0.w, a0.w);
            av[4] = pack2(a1.x, a1.x); av[5] = pack2(a1.y, a1.y);
            av[6] = pack2(a1.z, a1.z); av[7] = pack2(a1.w, a1.w);
            u64 bv[4];
            bv[0] = pack2(b0.x, b0.y); bv[1] = pack2(b0.z, b0.w);
            bv[2] = pack2(b1.x, b1.y); bv[3] = pack2(b1.z, b1.w);
            #pragma unroll
            for (int i = 0; i < 8; i++)
                #pragma unroll
                for (int j = 0; j < 4; j++)
                    fma2(c2[i][j], av[i], bv[j]);
        }
        if (kt + 1 < NT) {
            const int nx = cur ^ 1;
            As[nx][ak + 0][ar0] = pa0.x; As[nx][ak + 1][ar0] = pa0.y;
            As[nx][ak + 2][ar0] = pa0.z; As[nx][ak + 3][ar0] = pa0.w;
            As[nx][ak + 0][ar1] = pa1.x; As[nx][ak + 1][ar1] = pa1.y;
            As[nx][ak + 2][ar1] = pa1.z; As[nx][ak + 3][ar1] = pa1.w;
            *(float4*)&Bs[nx][bk0][bc0] = pb0;
            *(float4*)&Bs[nx][bk1][bc0] = pb1;
        }
        __syncthreads();
    }

    // ---- epilogue: bias + layout ----
    #pragma unroll
    for (int i = 0; i < 8; i++) {
        const int gr = row0 + ty * 8 + i;
        #pragma unroll
        for (int j = 0; j < 4; j++) {
            float v0, v1;
            unpack2(c2[i][j], v0, v1);
            const int c0 = n0 + tx * 8 + j * 2;
            v0 += bias[c0];
            v1 += bias[c0 + 1];
            if (mode == 0) {
                Cout[(size_t)gr * D + c0]     = v0;
                Cout[(size_t)gr * D + c0 + 1] = v1;
            } else {
                const int b = gr >> 11, s = gr & (S - 1);
                const int h = c0 >> 7, dd = c0 & (HD - 1);
                const size_t o = (((size_t)(b * H + h)) * S + s) * HD + dd;
                Cout[o]     = v0;
                Cout[o + 1] = v1;
            }
        }
    }
}

// ---------------------------------------------------------------------------
// Flash attention (causal): one CTA per (b*H+h, q-tile of 64 rows)
// 256 threads; K/V tiles of 64 streamed through dynamic smem; online softmax.
// Q pre-scaled by 1/sqrt(hd). All MACs in f32x2.
// Thread micro-tiles: scores 2x8 (rg=tid>>3 rows 2, cg=tid&7 cols 8),
//                     output  2x16.
// ---------------------------------------------------------------------------
constexpr int AM = 64, AN = 64;

struct __align__(16) AttnSmem {
    float Qt[HD][AM + 4];   // Q transposed [d][row], pre-scaled
    float Kt[HD][AN + 4];   // K transposed [d][col]
    float Vs[AN][HD];       // V row-major  [col][d]
    float Pt[AN][AM + 4];   // P transposed [col][row]
    float red[8][AM];       // per-cg row reductions
    float m_run[AM], l_run[AM], alphaS[AM], mnewS[AM];
};

__global__ __launch_bounds__(256, 1)
void attn_kernel(const float* __restrict__ Q, const float* __restrict__ Kg,
                 const float* __restrict__ Vg, float* __restrict__ Aout)
{
    extern __shared__ char smem_raw[];
    AttnSmem &sm = *reinterpret_cast<AttnSmem*>(smem_raw);

    const int tid = threadIdx.x;
    const int qb  = blockIdx.x;        // q tile
    const int bh  = blockIdx.y;        // b*H + h
    const int cg  = tid & 7;           // 0..7
    const int rg  = tid >> 3;          // 0..31

    const float SCALE = 0.08838834764831845f;  // 1/sqrt(128)
    const float* Qb = Q  + (size_t)bh * S * HD + (size_t)qb * AM * HD;
    const float* Kb = Kg + (size_t)bh * S * HD;
    const float* Vb = Vg + (size_t)bh * S * HD;

    if (tid < AM) { sm.m_run[tid] = -1e30f; sm.l_run[tid] = 0.f; }

    // stage Q (transposed + scaled), 2048 float4 over 256 threads
    #pragma unroll
    for (int f = tid; f < AM * HD / 4; f += 256) {
        const int row = f >> 5, q4 = (f & 31) * 4;
        float4 v = *(const float4*)&Qb[row * HD + q4];
        sm.Qt[q4 + 0][row] = v.x * SCALE;
        sm.Qt[q4 + 1][row] = v.y * SCALE;
        sm.Qt[q4 + 2][row] = v.z * SCALE;
        sm.Qt[q4 + 3][row] = v.w * SCALE;
    }

    u64 o2[2][8];
    #pragma unroll
    for (int i = 0; i < 2; i++)
        #pragma unroll
        for (int j = 0; j < 8; j++) o2[i][j] = 0ull;

    for (int kt = 0; kt <= qb; kt++) {
        __syncthreads();   // protect Kt/Vs/Pt/red from previous iteration's readers
        const float* Kt0 = Kb + (size_t)kt * AN * HD;
        const float* Vt0 = Vb + (size_t)kt * AN * HD;
        #pragma unroll
        for (int f = tid; f < AN * HD / 4; f += 256) {
            const int row = f >> 5, q4 = (f & 31) * 4;
            float4 kv = *(const float4*)&Kt0[row * HD + q4];
            sm.Kt[q4 + 0][row] = kv.x;
            sm.Kt[q4 + 1][row] = kv.y;
            sm.Kt[q4 + 2][row] = kv.z;
            sm.Kt[q4 + 3][row] = kv.w;
            *(float4*)&sm.Vs[row][q4] = *(const float4*)&Vt0[row * HD + q4];
        }
        __syncthreads();

        // ---- scores S = Qt^T Kt (2 rows x 8 cols per thread) ----
        u64 s2[2][4];
        #pragma unroll
        for (int i = 0; i < 2; i++)
            #pragma unroll
            for (int j = 0; j < 4; j++) s2[i][j] = 0ull;

        #pragma unroll 4
        for (int d = 0; d < HD; d++) {
            const float2 q  = *(const float2*)&sm.Qt[d][rg * 2];
            const float4 k0 = *(const float4*)&sm.Kt[d][cg * 8];
            const float4 k1 = *(const float4*)&sm.Kt[d][cg * 8 + 4];
            const u64 qa0 = pack2(q.x, q.x), qa1 = pack2(q.y, q.y);
            u64 kb[4];
            kb[0] = pack2(k0.x, k0.y); kb[1] = pack2(k0.z, k0.w);
            kb[2] = pack2(k1.x, k1.y); kb[3] = pack2(k1.z, k1.w);
            #pragma unroll
            for (int j = 0; j < 4; j++) {
                fma2(s2[0][j], qa0, kb[j]);
                fma2(s2[1][j], qa1, kb[j]);
            }
        }
        float s[2][8];
        #pragma unroll
        for (int i = 0; i < 2; i++)
            #pragma unroll
            for (int j = 0; j < 4; j++)
                unpack2(s2[i][j], s[i][2 * j], s[i][2 * j + 1]);

        if (kt == qb) {   // diagonal tile: mask col > row (tile-local compare)
            #pragma unroll
            for (int i = 0; i < 2; i++)
                #pragma unroll
                for (int j = 0; j < 8; j++)
                    if (cg * 8 + j > rg * 2 + i) s[i][j] = -1e30f;
        }

        // per-thread row maxima
        #pragma unroll
        for (int i = 0; i < 2; i++) {
            float pm = s[i][0];
            #pragma unroll
            for (int j = 1; j < 8; j++) pm = fmaxf(pm, s[i][j]);
            sm.red[cg][rg * 2 + i] = pm;
        }
        __syncthreads();

        if (tid < AM) {
            const float mo = sm.m_run[tid];
            float mn = mo;
            #pragma unroll
            for (int c = 0; c < 8; c++) mn = fmaxf(mn, sm.red[c][tid]);
            sm.m_run[tid]  = mn;
            sm.alphaS[tid] = __expf(mo - mn);
            sm.mnewS[tid]  = mn;
        }
        __syncthreads();

        // exp, write P^T, partial row sums
        #pragma unroll
        for (int i = 0; i < 2; i++) {
            const int row = rg * 2 + i;
            const float mn = sm.mnewS[row];
            float ps = 0.f;
            #pragma unroll
            for (int j = 0; j < 8; j++) {
                const float p = __expf(s[i][j] - mn);
                ps += p;
                sm.Pt[cg * 8 + j][row] = p;
            }
            sm.red[cg][row] = ps;
        }
        __syncthreads();

        if (tid < AM) {
            float ls = 0.f;
            #pragma unroll
            for (int c = 0; c < 8; c++) ls += sm.red[c][tid];
            sm.l_run[tid] = sm.l_run[tid] * sm.alphaS[tid] + ls;
        }

        // rescale running output by alpha
        #pragma unroll
        for (int i = 0; i < 2; i++) {
            const float al = sm.alphaS[rg * 2 + i];
            const u64 aa = pack2(al, al);
            #pragma unroll
            for (int jp = 0; jp < 8; jp++) o2[i][jp] = mul2(o2[i][jp], aa);
        }

        // ---- O += P V (2 rows x 16 cols per thread) ----
        #pragma unroll 2
        for (int c = 0; c < AN; c++) {
            const float2 p  = *(const float2*)&sm.Pt[c][rg * 2];
            const float4 v0 = *(const float4*)&sm.Vs[c][cg * 16];
            const float4 v1 = *(const float4*)&sm.Vs[c][cg * 16 + 4];
            const float4 v2 = *(const float4*)&sm.Vs[c][cg * 16 + 8];
            const float4 v3 = *(const float4*)&sm.Vs[c][cg * 16 + 12];
            const u64 pa0 = pack2(p.x, p.x), pa1 = pack2(p.y, p.y);
            u64 vb[8];
            vb[0] = pack2(v0.x, v0.y); vb[1] = pack2(v0.z, v0.w);
            vb[2] = pack2(v1.x, v1.y); vb[3] = pack2(v1.z, v1.w);
            vb[4] = pack2(v2.x, v2.y); vb[5] = pack2(v2.z, v2.w);
            vb[6] = pack2(v3.x, v3.y); vb[7] = pack2(v3.z, v3.w);
            #pragma unroll
            for (int jp = 0; jp < 8; jp++) {
                fma2(o2[0][jp], pa0, vb[jp]);
                fma2(o2[1][jp], pa1, vb[jp]);
            }
        }
    }

    __syncthreads();   // l_run final values visible to all

    const int b = bh >> 4, h = bh & 15;
    #pragma unroll
    for (int i = 0; i < 2; i++) {
        const int row = rg * 2 + i;
        const float inv = 1.f / sm.l_run[row];
        const int sglob = qb * AM + row;
        float* dst = Aout + ((size_t)(b * S + sglob)) * D + h * HD + cg * 16;
        #pragma unroll
        for (int jp = 0; jp < 8; jp++) {
            float x, y;
            unpack2(o2[i][jp], x, y);
            dst[jp * 2]     = x * inv;
            dst[jp * 2 + 1] = y * inv;
        }
    }
}

// ---------------------------------------------------------------------------
// Launch: QKV GEMMs (k/v scattered straight into d_out's `present` region),
// flash attention, output projection. 5 kernel launches, graph-capturable.
// ---------------------------------------------------------------------------
extern "C" void kernel_launch(void* const* d_in, const int* in_sizes, int n_in,
                              void* d_out, int out_size)
{
    const float* x  = (const float*)d_in[0];
    const float* Wq = (const float*)d_in[1];
    const float* bq = (const float*)d_in[2];
    const float* Wk = (const float*)d_in[3];
    const float* bk = (const float*)d_in[4];
    const float* Wv = (const float*)d_in[5];
    const float* bv = (const float*)d_in[6];
    const float* Wd = (const float*)d_in[7];
    const float* bd = (const float*)d_in[8];
    float* out = (float*)d_out;

    float *qp, *ap, *kp, *vp;
    cudaGetSymbolAddress((void**)&qp, g_q);
    cudaGetSymbolAddress((void**)&ap, g_a);
    if ((size_t)out_size >= 3 * A_SIZE) {
        kp = out + A_SIZE;          // present[0] = k  [B,H,S,hd]
        vp = out + 2 * A_SIZE;      // present[1] = v
    } else {
        cudaGetSymbolAddress((void**)&kp, g_k);
        cudaGetSymbolAddress((void**)&vp, g_v);
    }

    cudaFuncSetAttribute(attn_kernel,
                         cudaFuncAttributeMaxDynamicSharedMemorySize,
                         (int)sizeof(AttnSmem));

    dim3 gg(D / BN, MS / BM);                 // (16, 32)
    sgemm_kernel<<<gg, 256>>>(x, Wq, bq, qp, 1);
    sgemm_kernel<<<gg, 256>>>(x, Wk, bk, kp, 1);
    sgemm_kernel<<<gg, 256>>>(x, Wv, bv, vp, 1);

    attn_kernel<<<dim3(S / AM, Bb * H), 256, sizeof(AttnSmem)>>>(qp, kp, vp, ap);

    sgemm_kernel<<<gg, 256>>>(ap, Wd, bd, out, 0);
}

// round 13
// speedup vs baseline: 1.0003x; 1.0003x over previous
#include <cuda_runtime.h>

// ---------------------------------------------------------------------------
// Problem constants (fixed by the reference): B=2, S=2048, D=2048, H=16, hd=128
// ---------------------------------------------------------------------------
constexpr int Bb = 2;
constexpr int S  = 2048;
constexpr int D  = 2048;
constexpr int H  = 16;
constexpr int HD = 128;
constexpr int MS = Bb * S;                       // 4096 rows for projections
constexpr size_t A_SIZE = (size_t)Bb * S * D;   // 8388608

typedef unsigned long long u64;

// ---------------------------------------------------------------------------
// Packed f32x2 helpers (sm_103a: FFMA-3reg is half-rate; fma.rn.f32x2 restores
// full fp32 throughput — PTX-only, ptxas never auto-fuses)
// ---------------------------------------------------------------------------
__device__ __forceinline__ u64 pack2(float x, float y) {
    u64 r; asm("mov.b64 %0, {%1,%2};" : "=l"(r) : "f"(x), "f"(y)); return r;
}
__device__ __forceinline__ void unpack2(u64 v, float &x, float &y) {
    asm("mov.b64 {%0,%1}, %2;" : "=f"(x), "=f"(y) : "l"(v));
}
__device__ __forceinline__ void fma2(u64 &c, u64 a, u64 b) {
    asm("fma.rn.f32x2 %0, %1, %2, %3;" : "=l"(c) : "l"(a), "l"(b), "l"(c));
}
__device__ __forceinline__ u64 mul2(u64 a, u64 b) {
    u64 r; asm("mul.rn.f32x2 %0, %1, %2;" : "=l"(r) : "l"(a), "l"(b)); return r;
}

// ---------------------------------------------------------------------------
// Scratch (static __device__ arrays — no allocation allowed in kernel_launch)
// ---------------------------------------------------------------------------
__device__ float g_q[A_SIZE];   // Q in [B,H,S,hd]
__device__ float g_a[A_SIZE];   // attention result, merged heads [B,S,D]
__device__ float g_k[A_SIZE];   // fallback if out buffer has no present region
__device__ float g_v[A_SIZE];

// ---------------------------------------------------------------------------
// SGEMM: C[M=4096, N=2048] = A[M,K=2048] @ W[K,N] + bias
// 128x128 tile, BK=16, 256 threads, 8x8 per thread via f32x2,
// double-buffered smem with register prefetch.
// mode 0: row-major write to Cout[m*D + n]
// mode 1: scatter to [B,H,S,hd]:  Cout[((b*H+h)*S+s)*hd + dd]
// ---------------------------------------------------------------------------
constexpr int BM = 128, BN = 128, BK = 16;

__global__ __launch_bounds__(256, 2)
void sgemm_kernel(const float* __restrict__ A, const float* __restrict__ Bw,
                  const float* __restrict__ bias, float* __restrict__ Cout,
                  int mode)
{
    __shared__ __align__(16) float As[2][BK][BM + 4];
    __shared__ __align__(16) float Bs[2][BK][BN + 4];

    const int tid  = threadIdx.x;
    const int tx   = tid & 15;        // 0..15 -> 8 cols each
    const int ty   = tid >> 4;        // 0..15 -> 8 rows each
    const int row0 = blockIdx.y * BM;
    const int n0   = blockIdx.x * BN;

    // A tile: 128 rows x 16 k = 512 float4; this thread does f and f+256
    const int ar0 = tid >> 2;                 // 0..63
    const int ak  = (tid & 3) * 4;            // 0,4,8,12
    const int ar1 = ar0 + 64;                 // (tid+256)>>2, ak unchanged
    // B tile: 16 k x 128 cols = 512 float4
    const int bk0 = tid >> 5;                 // 0..7
    const int bc0 = (tid & 31) * 4;           // 0..124
    const int bk1 = bk0 + 8;                  // (tid+256)>>5, bc unchanged

    // ---- stage tile 0 directly into smem buffer 0 ----
    {
        float4 a0 = *(const float4*)&A[(size_t)(row0 + ar0) * D + ak];
        float4 a1 = *(const float4*)&A[(size_t)(row0 + ar1) * D + ak];
        float4 b0 = *(const float4*)&Bw[(size_t)bk0 * D + n0 + bc0];
        float4 b1 = *(const float4*)&Bw[(size_t)bk1 * D + n0 + bc0];
        As[0][ak + 0][ar0] = a0.x; As[0][ak + 1][ar0] = a0.y;
        As[0][ak + 2][ar0] = a0.z; As[0][ak + 3][ar0] = a0.w;
        As[0][ak + 0][ar1] = a1.x; As[0][ak + 1][ar1] = a1.y;
        As[0][ak + 2][ar1] = a1.z; As[0][ak + 3][ar1] = a1.w;
        *(float4*)&Bs[0][bk0][bc0] = b0;
        *(float4*)&Bs[0][bk1][bc0] = b1;
    }
    __syncthreads();

    u64 c2[8][4];
    #pragma unroll
    for (int i = 0; i < 8; i++)
        #pragma unroll
        for (int j = 0; j < 4; j++) c2[i][j] = 0ull;

    constexpr int NT = D / BK;   // 128 k-tiles
    float4 pa0, pa1, pb0, pb1;

    for (int kt = 0; kt < NT; kt++) {
        const int cur = kt & 1;
        if (kt + 1 < NT) {
            const int k0 = (kt + 1) * BK;
            pa0 = *(const float4*)&A[(size_t)(row0 + ar0) * D + k0 + ak];
            pa1 = *(const float4*)&A[(size_t)(row0 + ar1) * D + k0 + ak];
            pb0 = *(const float4*)&Bw[(size_t)(k0 + bk0) * D + n0 + bc0];
            pb1 = *(const float4*)&Bw[(size_t)(k0 + bk1) * D + n0 + bc0];
        }
        #pragma unroll
        for (int k = 0; k < BK; k++) {
            const float4 a0 = *(const float4*)&As[cur][k][ty * 8];
            const float4 a1 = *(const float4*)&As[cur][k][ty * 8 + 4];
            const float4 b0 = *(const float4*)&Bs[cur][k][tx * 8];
            const float4 b1 = *(const float4*)&Bs[cur][k][tx * 8 + 4];
            u64 av[8];
            av[0] = pack2(a0.x, a0.x); av[1] = pack2(a0.y, a0.y);
            av[2] = pack2(a0.z, a0.z); av[3] = pack2(a0.w, a0.w);
            av[4] = pack2(a1.x, a1.x); av[5] = pack2(a1.y, a1.y);
            av[6] = pack2(a1.z, a1.z); av[7] = pack2(a1.w, a1.w);
            u64 bv[4];
            bv[0] = pack2(b0.x, b0.y); bv[1] = pack2(b0.z, b0.w);
            bv[2] = pack2(b1.x, b1.y); bv[3] = pack2(b1.z, b1.w);
            #pragma unroll
            for (int i = 0; i < 8; i++)
                #pragma unroll
                for (int j = 0; j < 4; j++)
                    fma2(c2[i][j], av[i], bv[j]);
        }
        if (kt + 1 < NT) {
            const int nx = cur ^ 1;
            As[nx][ak + 0][ar0] = pa0.x; As[nx][ak + 1][ar0] = pa0.y;
            As[nx][ak + 2][ar0] = pa0.z; As[nx][ak + 3][ar0] = pa0.w;
            As[nx][ak + 0][ar1] = pa1.x; As[nx][ak + 1][ar1] = pa1.y;
            As[nx][ak + 2][ar1] = pa1.z; As[nx][ak + 3][ar1] = pa1.w;
            *(float4*)&Bs[nx][bk0][bc0] = pb0;
            *(float4*)&Bs[nx][bk1][bc0] = pb1;
        }
        __syncthreads();
    }

    // ---- epilogue: bias + layout ----
    #pragma unroll
    for (int i = 0; i < 8; i++) {
        const int gr = row0 + ty * 8 + i;
        #pragma unroll
        for (int j = 0; j < 4; j++) {
            float v0, v1;
            unpack2(c2[i][j], v0, v1);
            const int c0 = n0 + tx * 8 + j * 2;
            v0 += bias[c0];
            v1 += bias[c0 + 1];
            if (mode == 0) {
                Cout[(size_t)gr * D + c0]     = v0;
                Cout[(size_t)gr * D + c0 + 1] = v1;
            } else {
                const int b = gr >> 11, s = gr & (S - 1);
                const int h = c0 >> 7, dd = c0 & (HD - 1);
                const size_t o = (((size_t)(b * H + h)) * S + s) * HD + dd;
                Cout[o]     = v0;
                Cout[o + 1] = v1;
            }
        }
    }
}

// ---------------------------------------------------------------------------
// Flash attention (causal): one CTA per (b*H+h, q-tile of 64 rows)
// 256 threads; K/V tiles of 64 streamed through dynamic smem; online softmax.
// Q pre-scaled by 1/sqrt(hd). All MACs in f32x2.
// Thread micro-tiles: scores 2x8 (rg=tid>>3 rows 2, cg=tid&7 cols 8),
//                     output  2x16.
// ---------------------------------------------------------------------------
constexpr int AM = 64, AN = 64;

struct __align__(16) AttnSmem {
    float Qt[HD][AM + 4];   // Q transposed [d][row], pre-scaled
    float Kt[HD][AN + 4];   // K transposed [d][col]
    float Vs[AN][HD];       // V row-major  [col][d]
    float Pt[AN][AM + 4];   // P transposed [col][row]
    float red[8][AM];       // per-cg row reductions
    float m_run[AM], l_run[AM], alphaS[AM], mnewS[AM];
};

__global__ __launch_bounds__(256, 1)
void attn_kernel(const float* __restrict__ Q, const float* __restrict__ Kg,
                 const float* __restrict__ Vg, float* __restrict__ Aout)
{
    extern __shared__ char smem_raw[];
    AttnSmem &sm = *reinterpret_cast<AttnSmem*>(smem_raw);

    const int tid = threadIdx.x;
    const int qb  = blockIdx.x;        // q tile
    const int bh  = blockIdx.y;        // b*H + h
    const int cg  = tid & 7;           // 0..7
    const int rg  = tid >> 3;          // 0..31

    const float SCALE = 0.08838834764831845f;  // 1/sqrt(128)
    const float* Qb = Q  + (size_t)bh * S * HD + (size_t)qb * AM * HD;
    const float* Kb = Kg + (size_t)bh * S * HD;
    const float* Vb = Vg + (size_t)bh * S * HD;

    if (tid < AM) { sm.m_run[tid] = -1e30f; sm.l_run[tid] = 0.f; }

    // stage Q (transposed + scaled), 2048 float4 over 256 threads
    #pragma unroll
    for (int f = tid; f < AM * HD / 4; f += 256) {
        const int row = f >> 5, q4 = (f & 31) * 4;
        float4 v = *(const float4*)&Qb[row * HD + q4];
        sm.Qt[q4 + 0][row] = v.x * SCALE;
        sm.Qt[q4 + 1][row] = v.y * SCALE;
        sm.Qt[q4 + 2][row] = v.z * SCALE;
        sm.Qt[q4 + 3][row] = v.w * SCALE;
    }

    u64 o2[2][8];
    #pragma unroll
    for (int i = 0; i < 2; i++)
        #pragma unroll
        for (int j = 0; j < 8; j++) o2[i][j] = 0ull;

    for (int kt = 0; kt <= qb; kt++) {
        __syncthreads();   // protect Kt/Vs/Pt/red from previous iteration's readers
        const float* Kt0 = Kb + (size_t)kt * AN * HD;
        const float* Vt0 = Vb + (size_t)kt * AN * HD;
        #pragma unroll
        for (int f = tid; f < AN * HD / 4; f += 256) {
            const int row = f >> 5, q4 = (f & 31) * 4;
            float4 kv = *(const float4*)&Kt0[row * HD + q4];
            sm.Kt[q4 + 0][row] = kv.x;
            sm.Kt[q4 + 1][row] = kv.y;
            sm.Kt[q4 + 2][row] = kv.z;
            sm.Kt[q4 + 3][row] = kv.w;
            *(float4*)&sm.Vs[row][q4] = *(const float4*)&Vt0[row * HD + q4];
        }
        __syncthreads();

        // ---- scores S = Qt^T Kt (2 rows x 8 cols per thread) ----
        u64 s2[2][4];
        #pragma unroll
        for (int i = 0; i < 2; i++)
            #pragma unroll
            for (int j = 0; j < 4; j++) s2[i][j] = 0ull;

        #pragma unroll 4
        for (int d = 0; d < HD; d++) {
            const float2 q  = *(const float2*)&sm.Qt[d][rg * 2];
            const float4 k0 = *(const float4*)&sm.Kt[d][cg * 8];
            const float4 k1 = *(const float4*)&sm.Kt[d][cg * 8 + 4];
            const u64 qa0 = pack2(q.x, q.x), qa1 = pack2(q.y, q.y);
            u64 kb[4];
            kb[0] = pack2(k0.x, k0.y); kb[1] = pack2(k0.z, k0.w);
            kb[2] = pack2(k1.x, k1.y); kb[3] = pack2(k1.z, k1.w);
            #pragma unroll
            for (int j = 0; j < 4; j++) {
                fma2(s2[0][j], qa0, kb[j]);
                fma2(s2[1][j], qa1, kb[j]);
            }
        }
        float s[2][8];
        #pragma unroll
        for (int i = 0; i < 2; i++)
            #pragma unroll
            for (int j = 0; j < 4; j++)
                unpack2(s2[i][j], s[i][2 * j], s[i][2 * j + 1]);

        if (kt == qb) {   // diagonal tile: mask col > row (tile-local compare)
            #pragma unroll
            for (int i = 0; i < 2; i++)
                #pragma unroll
                for (int j = 0; j < 8; j++)
                    if (cg * 8 + j > rg * 2 + i) s[i][j] = -1e30f;
        }

        // per-thread row maxima
        #pragma unroll
        for (int i = 0; i < 2; i++) {
            float pm = s[i][0];
            #pragma unroll
            for (int j = 1; j < 8; j++) pm = fmaxf(pm, s[i][j]);
            sm.red[cg][rg * 2 + i] = pm;
        }
        __syncthreads();

        if (tid < AM) {
            const float mo = sm.m_run[tid];
            float mn = mo;
            #pragma unroll
            for (int c = 0; c < 8; c++) mn = fmaxf(mn, sm.red[c][tid]);
            sm.m_run[tid]  = mn;
            sm.alphaS[tid] = __expf(mo - mn);
            sm.mnewS[tid]  = mn;
        }
        __syncthreads();

        // exp, write P^T, partial row sums
        #pragma unroll
        for (int i = 0; i < 2; i++) {
            const int row = rg * 2 + i;
            const float mn = sm.mnewS[row];
            float ps = 0.f;
            #pragma unroll
            for (int j = 0; j < 8; j++) {
                const float p = __expf(s[i][j] - mn);
                ps += p;
                sm.Pt[cg * 8 + j][row] = p;
            }
            sm.red[cg][row] = ps;
        }
        __syncthreads();

        if (tid < AM) {
            float ls = 0.f;
            #pragma unroll
            for (int c = 0; c < 8; c++) ls += sm.red[c][tid];
            sm.l_run[tid] = sm.l_run[tid] * sm.alphaS[tid] + ls;
        }

        // rescale running output by alpha
        #pragma unroll
        for (int i = 0; i < 2; i++) {
            const float al = sm.alphaS[rg * 2 + i];
            const u64 aa = pack2(al, al);
            #pragma unroll
            for (int jp = 0; jp < 8; jp++) o2[i][jp] = mul2(o2[i][jp], aa);
        }

        // ---- O += P V (2 rows x 16 cols per thread) ----
        #pragma unroll 2
        for (int c = 0; c < AN; c++) {
            const float2 p  = *(const float2*)&sm.Pt[c][rg * 2];
            const float4 v0 = *(const float4*)&sm.Vs[c][cg * 16];
            const float4 v1 = *(const float4*)&sm.Vs[c][cg * 16 + 4];
            const float4 v2 = *(const float4*)&sm.Vs[c][cg * 16 + 8];
            const float4 v3 = *(const float4*)&sm.Vs[c][cg * 16 + 12];
            const u64 pa0 = pack2(p.x, p.x), pa1 = pack2(p.y, p.y);
            u64 vb[8];
            vb[0] = pack2(v0.x, v0.y); vb[1] = pack2(v0.z, v0.w);
            vb[2] = pack2(v1.x, v1.y); vb[3] = pack2(v1.z, v1.w);
            vb[4] = pack2(v2.x, v2.y); vb[5] = pack2(v2.z, v2.w);
            vb[6] = pack2(v3.x, v3.y); vb[7] = pack2(v3.z, v3.w);
            #pragma unroll
            for (int jp = 0; jp < 8; jp++) {
                fma2(o2[0][jp], pa0, vb[jp]);
                fma2(o2[1][jp], pa1, vb[jp]);
            }
        }
    }

    __syncthreads();   // l_run final values visible to all

    const int b = bh >> 4, h = bh & 15;
    #pragma unroll
    for (int i = 0; i < 2; i++) {
        const int row = rg * 2 + i;
        const float inv = 1.f / sm.l_run[row];
        const int sglob = qb * AM + row;
        float* dst = Aout + ((size_t)(b * S + sglob)) * D + h * HD + cg * 16;
        #pragma unroll
        for (int jp = 0; jp < 8; jp++) {
            float x, y;
            unpack2(o2[i][jp], x, y);
            dst[jp * 2]     = x * inv;
            dst[jp * 2 + 1] = y * inv;
        }
    }
}

// ---------------------------------------------------------------------------
// Launch: QKV GEMMs (k/v scattered straight into d_out's `present` region),
// flash attention, output projection. 5 kernel launches, graph-capturable.
// ---------------------------------------------------------------------------
extern "C" void kernel_launch(void* const* d_in, const int* in_sizes, int n_in,
                              void* d_out, int out_size)
{
    const float* x  = (const float*)d_in[0];
    const float* Wq = (const float*)d_in[1];
    const float* bq = (const float*)d_in[2];
    const float* Wk = (const float*)d_in[3];
    const float* bk = (const float*)d_in[4];
    const float* Wv = (const float*)d_in[5];
    const float* bv = (const float*)d_in[6];
    const float* Wd = (const float*)d_in[7];
    const float* bd = (const float*)d_in[8];
    float* out = (float*)d_out;

    float *qp, *ap, *kp, *vp;
    cudaGetSymbolAddress((void**)&qp, g_q);
    cudaGetSymbolAddress((void**)&ap, g_a);
    if ((size_t)out_size >= 3 * A_SIZE) {
        kp = out + A_SIZE;          // present[0] = k  [B,H,S,hd]
        vp = out + 2 * A_SIZE;      // present[1] = v
    } else {
        cudaGetSymbolAddress((void**)&kp, g_k);
        cudaGetSymbolAddress((void**)&vp, g_v);
    }

    cudaFuncSetAttribute(attn_kernel,
                         cudaFuncAttributeMaxDynamicSharedMemorySize,
                         (int)sizeof(AttnSmem));

    dim3 gg(D / BN, MS / BM);                 // (16, 32)
    sgemm_kernel<<<gg, 256>>>(x, Wq, bq, qp, 1);
    sgemm_kernel<<<gg, 256>>>(x, Wk, bk, kp, 1);
    sgemm_kernel<<<gg, 256>>>(x, Wv, bv, vp, 1);

    attn_kernel<<<dim3(S / AM, Bb * H), 256, sizeof(AttnSmem)>>>(qp, kp, vp, ap);

    sgemm_kernel<<<gg, 256>>>(ap, Wd, bd, out, 0);
}

// round 14
// speedup vs baseline: 1.0006x; 1.0003x over previous
#include <cuda_runtime.h>

// ---------------------------------------------------------------------------
// Problem constants (fixed by the reference): B=2, S=2048, D=2048, H=16, hd=128
// ---------------------------------------------------------------------------
constexpr int Bb = 2;
constexpr int S  = 2048;
constexpr int D  = 2048;
constexpr int H  = 16;
constexpr int HD = 128;
constexpr int MS = Bb * S;                       // 4096 rows for projections
constexpr size_t A_SIZE = (size_t)Bb * S * D;   // 8388608

typedef unsigned long long u64;

// ---------------------------------------------------------------------------
// Packed f32x2 helpers (sm_103a: FFMA-3reg is half-rate; fma.rn.f32x2 restores
// full fp32 throughput — PTX-only, ptxas never auto-fuses)
// ---------------------------------------------------------------------------
__device__ __forceinline__ u64 pack2(float x, float y) {
    u64 r; asm("mov.b64 %0, {%1,%2};" : "=l"(r) : "f"(x), "f"(y)); return r;
}
__device__ __forceinline__ void unpack2(u64 v, float &x, float &y) {
    asm("mov.b64 {%0,%1}, %2;" : "=f"(x), "=f"(y) : "l"(v));
}
__device__ __forceinline__ void fma2(u64 &c, u64 a, u64 b) {
    asm("fma.rn.f32x2 %0, %1, %2, %3;" : "=l"(c) : "l"(a), "l"(b), "l"(c));
}
__device__ __forceinline__ u64 mul2(u64 a, u64 b) {
    u64 r; asm("mul.rn.f32x2 %0, %1, %2;" : "=l"(r) : "l"(a), "l"(b)); return r;
}

// ---------------------------------------------------------------------------
// Scratch (static __device__ arrays — no allocation allowed in kernel_launch)
// ---------------------------------------------------------------------------
__device__ float g_q[A_SIZE];   // Q in [B,H,S,hd]
__device__ float g_a[A_SIZE];   // attention result, merged heads [B,S,D]
__device__ float g_k[A_SIZE];   // fallback if out buffer has no present region
__device__ float g_v[A_SIZE];

// ---------------------------------------------------------------------------
// SGEMM: C[M=4096, N=2048] = A[M,K=2048] @ W[K,N] + bias
// 128x128 tile, BK=16, 256 threads, 8x8 per thread via f32x2,
// double-buffered smem with register prefetch.
// mode 0: row-major write to Cout[m*D + n]
// mode 1: scatter to [B,H,S,hd]:  Cout[((b*H+h)*S+s)*hd + dd]
// ---------------------------------------------------------------------------
constexpr int BM = 128, BN = 128, BK = 16;

__global__ __launch_bounds__(256, 2)
void sgemm_kernel(const float* __restrict__ A, const float* __restrict__ Bw,
                  const float* __restrict__ bias, float* __restrict__ Cout,
                  int mode)
{
    __shared__ __align__(16) float As[2][BK][BM + 4];
    __shared__ __align__(16) float Bs[2][BK][BN + 4];

    const int tid  = threadIdx.x;
    const int tx   = tid & 15;        // 0..15 -> 8 cols each
    const int ty   = tid >> 4;        // 0..15 -> 8 rows each
    const int row0 = blockIdx.y * BM;
    const int n0   = blockIdx.x * BN;

    // A tile: 128 rows x 16 k = 512 float4; this thread does f and f+256
    const int ar0 = tid >> 2;                 // 0..63
    const int ak  = (tid & 3) * 4;            // 0,4,8,12
    const int ar1 = ar0 + 64;                 // (tid+256)>>2, ak unchanged
    // B tile: 16 k x 128 cols = 512 float4
    const int bk0 = tid >> 5;                 // 0..7
    const int bc0 = (tid & 31) * 4;           // 0..124
    const int bk1 = bk0 + 8;                  // (tid+256)>>5, bc unchanged

    // ---- stage tile 0 directly into smem buffer 0 ----
    {
        float4 a0 = *(const float4*)&A[(size_t)(row0 + ar0) * D + ak];
        float4 a1 = *(const float4*)&A[(size_t)(row0 + ar1) * D + ak];
        float4 b0 = *(const float4*)&Bw[(size_t)bk0 * D + n0 + bc0];
        float4 b1 = *(const float4*)&Bw[(size_t)bk1 * D + n0 + bc0];
        As[0][ak + 0][ar0] = a0.x; As[0][ak + 1][ar0] = a0.y;
        As[0][ak + 2][ar0] = a0.z; As[0][ak + 3][ar0] = a0.w;
        As[0][ak + 0][ar1] = a1.x; As[0][ak + 1][ar1] = a1.y;
        As[0][ak + 2][ar1] = a1.z; As[0][ak + 3][ar1] = a1.w;
        *(float4*)&Bs[0][bk0][bc0] = b0;
        *(float4*)&Bs[0][bk1][bc0] = b1;
    }
    __syncthreads();

    u64 c2[8][4];
    #pragma unroll
    for (int i = 0; i < 8; i++)
        #pragma unroll
        for (int j = 0; j < 4; j++) c2[i][j] = 0ull;

    constexpr int NT = D / BK;   // 128 k-tiles
    float4 pa0, pa1, pb0, pb1;

    for (int kt = 0; kt < NT; kt++) {
        const int cur = kt & 1;
        if (kt + 1 < NT) {
            const int k0 = (kt + 1) * BK;
            pa0 = *(const float4*)&A[(size_t)(row0 + ar0) * D + k0 + ak];
            pa1 = *(const float4*)&A[(size_t)(row0 + ar1) * D + k0 + ak];
            pb0 = *(const float4*)&Bw[(size_t)(k0 + bk0) * D + n0 + bc0];
            pb1 = *(const float4*)&Bw[(size_t)(k0 + bk1) * D + n0 + bc0];
        }
        #pragma unroll
        for (int k = 0; k < BK; k++) {
            const float4 a0 = *(const float4*)&As[cur][k][ty * 8];
            const float4 a1 = *(const float4*)&As[cur][k][ty * 8 + 4];
            const float4 b0 = *(const float4*)&Bs[cur][k][tx * 8];
            const float4 b1 = *(const float4*)&Bs[cur][k][tx * 8 + 4];
            u64 av[8];
            av[0] = pack2(a0.x, a0.x); av[1] = pack2(a0.y, a0.y);
            av[2] = pack2(a0.z, a0.z); av[3] = pack2(a0.w, a0.w);
            av[4] = pack2(a1.x, a1.x); av[5] = pack2(a1.y, a1.y);
            av[6] = pack2(a1.z, a1.z); av[7] = pack2(a1.w, a1.w);
            u64 bv[4];
            bv[0] = pack2(b0.x, b0.y); bv[1] = pack2(b0.z, b0.w);
            bv[2] = pack2(b1.x, b1.y); bv[3] = pack2(b1.z, b1.w);
            #pragma unroll
            for (int i = 0; i < 8; i++)
                #pragma unroll
                for (int j = 0; j < 4; j++)
                    fma2(c2[i][j], av[i], bv[j]);
        }
        if (kt + 1 < NT) {
            const int nx = cur ^ 1;
            As[nx][ak + 0][ar0] = pa0.x; As[nx][ak + 1][ar0] = pa0.y;
            As[nx][ak + 2][ar0] = pa0.z; As[nx][ak + 3][ar0] = pa0.w;
            As[nx][ak + 0][ar1] = pa1.x; As[nx][ak + 1][ar1] = pa1.y;
            As[nx][ak + 2][ar1] = pa1.z; As[nx][ak + 3][ar1] = pa1.w;
            *(float4*)&Bs[nx][bk0][bc0] = pb0;
            *(float4*)&Bs[nx][bk1][bc0] = pb1;
        }
        __syncthreads();
    }

    // ---- epilogue: bias + layout ----
    #pragma unroll
    for (int i = 0; i < 8; i++) {
        const int gr = row0 + ty * 8 + i;
        #pragma unroll
        for (int j = 0; j < 4; j++) {
            float v0, v1;
            unpack2(c2[i][j], v0, v1);
            const int c0 = n0 + tx * 8 + j * 2;
            v0 += bias[c0];
            v1 += bias[c0 + 1];
            if (mode == 0) {
                Cout[(size_t)gr * D + c0]     = v0;
                Cout[(size_t)gr * D + c0 + 1] = v1;
            } else {
                const int b = gr >> 11, s = gr & (S - 1);
                const int h = c0 >> 7, dd = c0 & (HD - 1);
                const size_t o = (((size_t)(b * H + h)) * S + s) * HD + dd;
                Cout[o]     = v0;
                Cout[o + 1] = v1;
            }
        }
    }
}

// ---------------------------------------------------------------------------
// Flash attention (causal): one CTA per (b*H+h, q-tile of 64 rows)
// 256 threads; K/V tiles of 64 streamed through dynamic smem; online softmax.
// Q pre-scaled by 1/sqrt(hd). All MACs in f32x2.
// Thread micro-tiles: scores 2x8 (rg=tid>>3 rows 2, cg=tid&7 cols 8),
//                     output  2x16.
// ---------------------------------------------------------------------------
constexpr int AM = 64, AN = 64;

struct __align__(16) AttnSmem {
    float Qt[HD][AM + 4];   // Q transposed [d][row], pre-scaled
    float Kt[HD][AN + 4];   // K transposed [d][col]
    float Vs[AN][HD];       // V row-major  [col][d]
    float Pt[AN][AM + 4];   // P transposed [col][row]
    float red[8][AM];       // per-cg row reductions
    float m_run[AM], l_run[AM], alphaS[AM], mnewS[AM];
};

__global__ __launch_bounds__(256, 1)
void attn_kernel(const float* __restrict__ Q, const float* __restrict__ Kg,
                 const float* __restrict__ Vg, float* __restrict__ Aout)
{
    extern __shared__ char smem_raw[];
    AttnSmem &sm = *reinterpret_cast<AttnSmem*>(smem_raw);

    const int tid = threadIdx.x;
    const int qb  = blockIdx.x;        // q tile
    const int bh  = blockIdx.y;        // b*H + h
    const int cg  = tid & 7;           // 0..7
    const int rg  = tid >> 3;          // 0..31

    const float SCALE = 0.08838834764831845f;  // 1/sqrt(128)
    const float* Qb = Q  + (size_t)bh * S * HD + (size_t)qb * AM * HD;
    const float* Kb = Kg + (size_t)bh * S * HD;
    const float* Vb = Vg + (size_t)bh * S * HD;

    if (tid < AM) { sm.m_run[tid] = -1e30f; sm.l_run[tid] = 0.f; }

    // stage Q (transposed + scaled), 2048 float4 over 256 threads
    #pragma unroll
    for (int f = tid; f < AM * HD / 4; f += 256) {
        const int row = f >> 5, q4 = (f & 31) * 4;
        float4 v = *(const float4*)&Qb[row * HD + q4];
        sm.Qt[q4 + 0][row] = v.x * SCALE;
        sm.Qt[q4 + 1][row] = v.y * SCALE;
        sm.Qt[q4 + 2][row] = v.z * SCALE;
        sm.Qt[q4 + 3][row] = v.w * SCALE;
    }

    u64 o2[2][8];
    #pragma unroll
    for (int i = 0; i < 2; i++)
        #pragma unroll
        for (int j = 0; j < 8; j++) o2[i][j] = 0ull;

    for (int kt = 0; kt <= qb; kt++) {
        __syncthreads();   // protect Kt/Vs/Pt/red from previous iteration's readers
        const float* Kt0 = Kb + (size_t)kt * AN * HD;
        const float* Vt0 = Vb + (size_t)kt * AN * HD;
        #pragma unroll
        for (int f = tid; f < AN * HD / 4; f += 256) {
            const int row = f >> 5, q4 = (f & 31) * 4;
            float4 kv = *(const float4*)&Kt0[row * HD + q4];
            sm.Kt[q4 + 0][row] = kv.x;
            sm.Kt[q4 + 1][row] = kv.y;
            sm.Kt[q4 + 2][row] = kv.z;
            sm.Kt[q4 + 3][row] = kv.w;
            *(float4*)&sm.Vs[row][q4] = *(const float4*)&Vt0[row * HD + q4];
        }
        __syncthreads();

        // ---- scores S = Qt^T Kt (2 rows x 8 cols per thread) ----
        u64 s2[2][4];
        #pragma unroll
        for (int i = 0; i < 2; i++)
            #pragma unroll
            for (int j = 0; j < 4; j++) s2[i][j] = 0ull;

        #pragma unroll 4
        for (int d = 0; d < HD; d++) {
            const float2 q  = *(const float2*)&sm.Qt[d][rg * 2];
            const float4 k0 = *(const float4*)&sm.Kt[d][cg * 8];
            const float4 k1 = *(const float4*)&sm.Kt[d][cg * 8 + 4];
            const u64 qa0 = pack2(q.x, q.x), qa1 = pack2(q.y, q.y);
            u64 kb[4];
            kb[0] = pack2(k0.x, k0.y); kb[1] = pack2(k0.z, k0.w);
            kb[2] = pack2(k1.x, k1.y); kb[3] = pack2(k1.z, k1.w);
            #pragma unroll
            for (int j = 0; j < 4; j++) {
                fma2(s2[0][j], qa0, kb[j]);
                fma2(s2[1][j], qa1, kb[j]);
            }
        }
        float s[2][8];
        #pragma unroll
        for (int i = 0; i < 2; i++)
            #pragma unroll
            for (int j = 0; j < 4; j++)
                unpack2(s2[i][j], s[i][2 * j], s[i][2 * j + 1]);

        if (kt == qb) {   // diagonal tile: mask col > row (tile-local compare)
            #pragma unroll
            for (int i = 0; i < 2; i++)
                #pragma unroll
                for (int j = 0; j < 8; j++)
                    if (cg * 8 + j > rg * 2 + i) s[i][j] = -1e30f;
        }

        // per-thread row maxima
        #pragma unroll
        for (int i = 0; i < 2; i++) {
            float pm = s[i][0];
            #pragma unroll
            for (int j = 1; j < 8; j++) pm = fmaxf(pm, s[i][j]);
            sm.red[cg][rg * 2 + i] = pm;
        }
        __syncthreads();

        if (tid < AM) {
            const float mo = sm.m_run[tid];
            float mn = mo;
            #pragma unroll
            for (int c = 0; c < 8; c++) mn = fmaxf(mn, sm.red[c][tid]);
            sm.m_run[tid]  = mn;
            sm.alphaS[tid] = __expf(mo - mn);
            sm.mnewS[tid]  = mn;
        }
        __syncthreads();

        // exp, write P^T, partial row sums
        #pragma unroll
        for (int i = 0; i < 2; i++) {
            const int row = rg * 2 + i;
            const float mn = sm.mnewS[row];
            float ps = 0.f;
            #pragma unroll
            for (int j = 0; j < 8; j++) {
                const float p = __expf(s[i][j] - mn);
                ps += p;
                sm.Pt[cg * 8 + j][row] = p;
            }
            sm.red[cg][row] = ps;
        }
        __syncthreads();

        if (tid < AM) {
            float ls = 0.f;
            #pragma unroll
            for (int c = 0; c < 8; c++) ls += sm.red[c][tid];
            sm.l_run[tid] = sm.l_run[tid] * sm.alphaS[tid] + ls;
        }

        // rescale running output by alpha
        #pragma unroll
        for (int i = 0; i < 2; i++) {
            const float al = sm.alphaS[rg * 2 + i];
            const u64 aa = pack2(al, al);
            #pragma unroll
            for (int jp = 0; jp < 8; jp++) o2[i][jp] = mul2(o2[i][jp], aa);
        }

        // ---- O += P V (2 rows x 16 cols per thread) ----
        #pragma unroll 2
        for (int c = 0; c < AN; c++) {
            const float2 p  = *(const float2*)&sm.Pt[c][rg * 2];
            const float4 v0 = *(const float4*)&sm.Vs[c][cg * 16];
            const float4 v1 = *(const float4*)&sm.Vs[c][cg * 16 + 4];
            const float4 v2 = *(const float4*)&sm.Vs[c][cg * 16 + 8];
            const float4 v3 = *(const float4*)&sm.Vs[c][cg * 16 + 12];
            const u64 pa0 = pack2(p.x, p.x), pa1 = pack2(p.y, p.y);
            u64 vb[8];
            vb[0] = pack2(v0.x, v0.y); vb[1] = pack2(v0.z, v0.w);
            vb[2] = pack2(v1.x, v1.y); vb[3] = pack2(v1.z, v1.w);
            vb[4] = pack2(v2.x, v2.y); vb[5] = pack2(v2.z, v2.w);
            vb[6] = pack2(v3.x, v3.y); vb[7] = pack2(v3.z, v3.w);
            #pragma unroll
            for (int jp = 0; jp < 8; jp++) {
                fma2(o2[0][jp], pa0, vb[jp]);
                fma2(o2[1][jp], pa1, vb[jp]);
            }
        }
    }

    __syncthreads();   // l_run final values visible to all

    const int b = bh >> 4, h = bh & 15;
    #pragma unroll
    for (int i = 0; i < 2; i++) {
        const int row = rg * 2 + i;
        const float inv = 1.f / sm.l_run[row];
        const int sglob = qb * AM + row;
        float* dst = Aout + ((size_t)(b * S + sglob)) * D + h * HD + cg * 16;
        #pragma unroll
        for (int jp = 0; jp < 8; jp++) {
            float x, y;
            unpack2(o2[i][jp], x, y);
            dst[jp * 2]     = x * inv;
            dst[jp * 2 + 1] = y * inv;
        }
    }
}

// ---------------------------------------------------------------------------
// Launch: QKV GEMMs (k/v scattered straight into d_out's `present` region),
// flash attention, output projection. 5 kernel launches, graph-capturable.
// ---------------------------------------------------------------------------
extern "C" void kernel_launch(void* const* d_in, const int* in_sizes, int n_in,
                              void* d_out, int out_size)
{
    const float* x  = (const float*)d_in[0];
    const float* Wq = (const float*)d_in[1];
    const float* bq = (const float*)d_in[2];
    const float* Wk = (const float*)d_in[3];
    const float* bk = (const float*)d_in[4];
    const float* Wv = (const float*)d_in[5];
    const float* bv = (const float*)d_in[6];
    const float* Wd = (const float*)d_in[7];
    const float* bd = (const float*)d_in[8];
    float* out = (float*)d_out;

    float *qp, *ap, *kp, *vp;
    cudaGetSymbolAddress((void**)&qp, g_q);
    cudaGetSymbolAddress((void**)&ap, g_a);
    if ((size_t)out_size >= 3 * A_SIZE) {
        kp = out + A_SIZE;          // present[0] = k  [B,H,S,hd]
        vp = out + 2 * A_SIZE;      // present[1] = v
    } else {
        cudaGetSymbolAddress((void**)&kp, g_k);
        cudaGetSymbolAddress((void**)&vp, g_v);
    }

    cudaFuncSetAttribute(attn_kernel,
                         cudaFuncAttributeMaxDynamicSharedMemorySize,
                         (int)sizeof(AttnSmem));

    dim3 gg(D / BN, MS / BM);                 // (16, 32)
    sgemm_kernel<<<gg, 256>>>(x, Wq, bq, qp, 1);
    sgemm_kernel<<<gg, 256>>>(x, Wk, bk, kp, 1);
    sgemm_kernel<<<gg, 256>>>(x, Wv, bv, vp, 1);

    attn_kernel<<<dim3(S / AM, Bb * H), 256, sizeof(AttnSmem)>>>(qp, kp, vp, ap);

    sgemm_kernel<<<gg, 256>>>(ap, Wd, bd, out, 0);
}